// round 1
// baseline (speedup 1.0000x reference)
#include <cuda_runtime.h>
#include <cuda_bf16.h>
#include <math.h>

// ---------------- problem constants ----------------
#define D_MODEL 256
#define NH 8
#define HD 32
#define NL 4
#define NP 4
#define DFF 1024
#define B_SZ 2
#define LT 20
#define LQ_C 20197
#define NTOK (B_SZ * LQ_C)   // 40394

// level shapes / starts
__device__ __constant__ int c_H[NL]  = {100, 50, 25, 13};
__device__ __constant__ int c_W[NL]  = {152, 76, 38, 19};
__device__ __constant__ int c_St[NL] = {0, 15200, 19000, 19950};

// ---------------- scratch (static device globals; no allocation) ----------------
__device__ float g_q[NTOK * D_MODEL];      // q=src+pos; later reused for ms out, then qh
__device__ float g_value[NTOK * D_MODEL];  // value proj; later reused x+pos, pre-LN sums
__device__ float g_offs[NTOK * D_MODEL];   // sampling offsets; later reused pre-LN1 sum, ctx
__device__ float g_aw[NTOK * 128];         // attention weights (logits -> softmax in place)
__device__ float g_hid[NTOK * DFF];        // FFN hidden
__device__ float g_kh[B_SZ * LT * D_MODEL];
__device__ float g_vh[B_SZ * LT * D_MODEL];

static inline int cdiv(int a, int b) { return (a + b - 1) / b; }

// ---------------- elementwise add ----------------
__global__ void add_kernel(const float* __restrict__ a, const float* __restrict__ b,
                           float* __restrict__ out, int n) {
    int i = blockIdx.x * blockDim.x + threadIdx.x;
    if (i < n) out[i] = a[i] + b[i];
}

// ---------------- GEMM: C[M,N] = A[M,K] @ W[N,K]^T + bias (+residual / relu) ----------------
// MODE 0: +bias; MODE 1: +bias+residual; MODE 2: +bias, relu
#define BM 128
#define BN 64
#define BK 16
template <int MODE>
__global__ void gemm_kernel(const float* __restrict__ A, const float* __restrict__ W,
                            const float* __restrict__ bias, const float* __restrict__ R,
                            float* __restrict__ C, int M, int N, int K) {
    __shared__ float As[BK][BM];
    __shared__ float Ws[BK][BN];
    int tid = threadIdx.x;
    int ty = tid >> 4;           // 0..15 -> 8 rows each
    int tx = tid & 15;           // 0..15 -> 4 cols each
    int rowBase = blockIdx.y * BM;
    int colBase = blockIdx.x * BN;

    float acc[8][4];
#pragma unroll
    for (int m = 0; m < 8; m++)
#pragma unroll
        for (int n = 0; n < 4; n++) acc[m][n] = 0.f;

    for (int k0 = 0; k0 < K; k0 += BK) {
        // load A tile (128x16) : 2048 elems / 256 threads = 8 each
#pragma unroll
        for (int i = 0; i < 8; i++) {
            int idx = tid + i * 256;
            int r = idx >> 4, kk = idx & 15;
            int gr = rowBase + r;
            As[kk][r] = (gr < M) ? A[(long)gr * K + k0 + kk] : 0.f;
        }
        // load W tile (64x16) : 1024 / 256 = 4 each
#pragma unroll
        for (int i = 0; i < 4; i++) {
            int idx = tid + i * 256;
            int r = idx >> 4, kk = idx & 15;
            int gc = colBase + r;
            Ws[kk][r] = (gc < N) ? W[(long)gc * K + k0 + kk] : 0.f;
        }
        __syncthreads();
#pragma unroll
        for (int kk = 0; kk < BK; kk++) {
            float a[8], w[4];
#pragma unroll
            for (int m = 0; m < 8; m++) a[m] = As[kk][ty * 8 + m];
#pragma unroll
            for (int n = 0; n < 4; n++) w[n] = Ws[kk][tx * 4 + n];
#pragma unroll
            for (int m = 0; m < 8; m++)
#pragma unroll
                for (int n = 0; n < 4; n++) acc[m][n] += a[m] * w[n];
        }
        __syncthreads();
    }

#pragma unroll
    for (int m = 0; m < 8; m++) {
        int row = rowBase + ty * 8 + m;
        if (row >= M) continue;
#pragma unroll
        for (int n = 0; n < 4; n++) {
            int col = colBase + tx * 4 + n;
            if (col >= N) continue;
            float v = acc[m][n] + bias[col];
            if (MODE == 1) v += R[(long)row * N + col];
            if (MODE == 2) v = fmaxf(v, 0.f);
            C[(long)row * N + col] = v;
        }
    }
}

// ---------------- softmax over 16 per (token, head) ----------------
__global__ void softmax16_kernel(float* __restrict__ aw) {
    int idx = blockIdx.x * blockDim.x + threadIdx.x;
    if (idx >= NTOK * NH) return;
    int token = idx >> 3, h = idx & 7;
    float* p = aw + (long)token * 128 + h * 16;
    float mx = -1e30f;
#pragma unroll
    for (int i = 0; i < 16; i++) mx = fmaxf(mx, p[i]);
    float s = 0.f, e[16];
#pragma unroll
    for (int i = 0; i < 16; i++) { e[i] = expf(p[i] - mx); s += e[i]; }
    float inv = 1.f / s;
#pragma unroll
    for (int i = 0; i < 16; i++) p[i] = e[i] * inv;
}

// ---------------- multi-scale deformable sampling: warp per (token, head) ----------------
__global__ void msdeform_kernel(const float* __restrict__ value, const float* __restrict__ offs,
                                const float* __restrict__ aw, const float* __restrict__ ref,
                                float* __restrict__ out) {
    int gw = (blockIdx.x * blockDim.x + threadIdx.x) >> 5;
    int lane = threadIdx.x & 31;
    if (gw >= NTOK * NH) return;
    int token = gw >> 3, h = gw & 7;
    int b = token / LQ_C;

    const float* rp = ref + (long)token * (NL * 2);
    const float* of = offs + (long)token * 256 + h * 32;
    const float* awp = aw + (long)token * 128 + h * 16;

    float acc = 0.f;
#pragma unroll
    for (int l = 0; l < NL; l++) {
        int Wl = c_W[l], Hl = c_H[l];
        float Wf = (float)Wl, Hf = (float)Hl;
        float rx = rp[l * 2 + 0], ry = rp[l * 2 + 1];
        long base = (long)b * LQ_C + c_St[l];
#pragma unroll
        for (int p = 0; p < NP; p++) {
            float ox = of[(l * 4 + p) * 2 + 0];
            float oy = of[(l * 4 + p) * 2 + 1];
            float wA = awp[l * 4 + p];
            float X = (rx + ox / Wf) * Wf - 0.5f;
            float Y = (ry + oy / Hf) * Hf - 0.5f;
            float x0f = floorf(X), y0f = floorf(Y);
            float lx = X - x0f, ly = Y - y0f;
            int x0 = (int)x0f, y0 = (int)y0f;
            float ps = 0.f;
            // corners: (dy,dx,w)
            {
                float w = (1.f - lx) * (1.f - ly);
                int xi = x0, yi = y0;
                if (xi >= 0 && xi < Wl && yi >= 0 && yi < Hl)
                    ps += w * value[(base + (long)yi * Wl + xi) * 256 + h * 32 + lane];
            }
            {
                float w = lx * (1.f - ly);
                int xi = x0 + 1, yi = y0;
                if (xi >= 0 && xi < Wl && yi >= 0 && yi < Hl)
                    ps += w * value[(base + (long)yi * Wl + xi) * 256 + h * 32 + lane];
            }
            {
                float w = (1.f - lx) * ly;
                int xi = x0, yi = y0 + 1;
                if (xi >= 0 && xi < Wl && yi >= 0 && yi < Hl)
                    ps += w * value[(base + (long)yi * Wl + xi) * 256 + h * 32 + lane];
            }
            {
                float w = lx * ly;
                int xi = x0 + 1, yi = y0 + 1;
                if (xi >= 0 && xi < Wl && yi >= 0 && yi < Hl)
                    ps += w * value[(base + (long)yi * Wl + xi) * 256 + h * 32 + lane];
            }
            acc += wA * ps;
        }
    }
    out[(long)token * 256 + h * 32 + lane] = acc;
}

// ---------------- layernorm: warp per row (256 cols) ----------------
__global__ void ln_kernel(const float* __restrict__ in, const float* __restrict__ g,
                          const float* __restrict__ b, float* __restrict__ out, int rows) {
    int warp = (blockIdx.x * blockDim.x + threadIdx.x) >> 5;
    int lane = threadIdx.x & 31;
    if (warp >= rows) return;
    const float* x = in + (long)warp * 256;
    float v[8];
    float s = 0.f;
#pragma unroll
    for (int j = 0; j < 8; j++) { v[j] = x[j * 32 + lane]; s += v[j]; }
#pragma unroll
    for (int o = 16; o; o >>= 1) s += __shfl_xor_sync(0xffffffffu, s, o);
    float m = s * (1.f / 256.f);
    float s2 = 0.f;
#pragma unroll
    for (int j = 0; j < 8; j++) { float d = v[j] - m; s2 += d * d; }
#pragma unroll
    for (int o = 16; o; o >>= 1) s2 += __shfl_xor_sync(0xffffffffu, s2, o);
    float rstd = rsqrtf(s2 * (1.f / 256.f) + 1e-5f);
#pragma unroll
    for (int j = 0; j < 8; j++) {
        int col = j * 32 + lane;
        out[(long)warp * 256 + col] = (v[j] - m) * rstd * g[col] + b[col];
    }
}

// ---------------- text K/V projection (40 rows) ----------------
__global__ void kv_proj_kernel(const float* __restrict__ text, const float* __restrict__ ipw,
                               const float* __restrict__ ipb, float* __restrict__ kh,
                               float* __restrict__ vh) {
    int row = blockIdx.x;   // 0..B*LT-1
    int c = threadIdx.x;    // 0..255
    const float* t = text + (long)row * 256;
    const float* wk = ipw + (long)(256 + c) * 256;
    const float* wv = ipw + (long)(512 + c) * 256;
    float sk = ipb[256 + c], sv = ipb[512 + c];
    for (int k = 0; k < 256; k++) {
        float tv = t[k];
        sk += tv * wk[k];
        sv += tv * wv[k];
    }
    kh[(long)row * 256 + c] = sk;
    vh[(long)row * 256 + c] = sv;
}

// ---------------- text cross-attention: thread per (token, head), K=20 ----------------
__global__ void cross_attn_kernel(const float* __restrict__ qh, const float* __restrict__ kh,
                                  const float* __restrict__ vh, float* __restrict__ ctx) {
    int idx = blockIdx.x * blockDim.x + threadIdx.x;
    if (idx >= NTOK * NH) return;
    int token = idx >> 3, h = idx & 7;
    int b = token / LQ_C;
    const float* q = qh + (long)token * 256 + h * 32;
    float qv[32];
#pragma unroll
    for (int d = 0; d < 32; d++) qv[d] = q[d];

    float sc[LT];
    float mx = -1e30f;
    const float scale = 0.17677669529663687f;  // 1/sqrt(32)
#pragma unroll 4
    for (int k = 0; k < LT; k++) {
        const float* kp = kh + (long)(b * LT + k) * 256 + h * 32;
        float s = 0.f;
#pragma unroll
        for (int d = 0; d < 32; d++) s += qv[d] * kp[d];
        s *= scale;
        sc[k] = s;
        mx = fmaxf(mx, s);
    }
    float denom = 0.f;
#pragma unroll
    for (int k = 0; k < LT; k++) { sc[k] = expf(sc[k] - mx); denom += sc[k]; }
    float inv = 1.f / denom;
    float o[32];
#pragma unroll
    for (int d = 0; d < 32; d++) o[d] = 0.f;
#pragma unroll 4
    for (int k = 0; k < LT; k++) {
        float p = sc[k] * inv;
        const float* vp = vh + (long)(b * LT + k) * 256 + h * 32;
#pragma unroll
        for (int d = 0; d < 32; d++) o[d] += p * vp[d];
    }
#pragma unroll
    for (int d = 0; d < 32; d++) ctx[(long)token * 256 + h * 32 + d] = o[d];
}

// ---------------- launch ----------------
extern "C" void kernel_launch(void* const* d_in, const int* in_sizes, int n_in,
                              void* d_out, int out_size) {
    const float* src   = (const float*)d_in[0];
    const float* pos   = (const float*)d_in[1];
    const float* refp  = (const float*)d_in[2];
    // d_in[3] spatial_shapes, d_in[4] level_start_index: compile-time constants
    const float* text  = (const float*)d_in[5];
    // d_in[6] text_mask: all-false, unused by reference softmax
    const float* so_w  = (const float*)d_in[7];
    const float* so_b  = (const float*)d_in[8];
    const float* aw_w  = (const float*)d_in[9];
    const float* aw_b  = (const float*)d_in[10];
    const float* vp_w  = (const float*)d_in[11];
    const float* vp_b  = (const float*)d_in[12];
    const float* op_w  = (const float*)d_in[13];
    const float* op_b  = (const float*)d_in[14];
    const float* ln1_g = (const float*)d_in[15];
    const float* ln1_b = (const float*)d_in[16];
    const float* ipw   = (const float*)d_in[17];
    const float* ipb   = (const float*)d_in[18];
    const float* mo_w  = (const float*)d_in[19];
    const float* mo_b  = (const float*)d_in[20];
    const float* ln3_g = (const float*)d_in[21];
    const float* ln3_b = (const float*)d_in[22];
    const float* l1_w  = (const float*)d_in[23];
    const float* l1_b  = (const float*)d_in[24];
    const float* l2_w  = (const float*)d_in[25];
    const float* l2_b  = (const float*)d_in[26];
    const float* ln2_g = (const float*)d_in[27];
    const float* ln2_b = (const float*)d_in[28];

    float* out_x = (float*)d_out;                         // [NTOK, 256]
    float* out_text = out_x + (long)NTOK * D_MODEL;       // [B*LT, 256]

    float *q, *val, *offs, *aw, *hid, *kh, *vh;
    cudaGetSymbolAddress((void**)&q, g_q);
    cudaGetSymbolAddress((void**)&val, g_value);
    cudaGetSymbolAddress((void**)&offs, g_offs);
    cudaGetSymbolAddress((void**)&aw, g_aw);
    cudaGetSymbolAddress((void**)&hid, g_hid);
    cudaGetSymbolAddress((void**)&kh, g_kh);
    cudaGetSymbolAddress((void**)&vh, g_vh);

    const int M = NTOK;
    const int nElem = M * D_MODEL;
    dim3 gemmGrid256(cdiv(D_MODEL, BN), cdiv(M, BM));
    dim3 gemmGrid128(cdiv(128, BN), cdiv(M, BM));
    dim3 gemmGrid1024(cdiv(DFF, BN), cdiv(M, BM));

    // 1) q = src + pos
    add_kernel<<<cdiv(nElem, 256), 256>>>(src, pos, q, nElem);
    // 2) value = src @ vp^T + b
    gemm_kernel<0><<<gemmGrid256, 256>>>(src, vp_w, vp_b, nullptr, val, M, 256, 256);
    // 3) offs = q @ so^T + b
    gemm_kernel<0><<<gemmGrid256, 256>>>(q, so_w, so_b, nullptr, offs, M, 256, 256);
    // 4) aw logits + softmax(16)
    gemm_kernel<0><<<gemmGrid128, 256>>>(q, aw_w, aw_b, nullptr, aw, M, 128, 256);
    softmax16_kernel<<<cdiv(M * NH, 256), 256>>>(aw);
    // 5) deformable sampling -> ms (reuse q)
    msdeform_kernel<<<cdiv(M * NH * 32, 256), 256>>>(val, offs, aw, refp, q);
    // 6) pre-LN1 = ms @ op^T + b + src  -> offs ; LN1 -> out_x
    gemm_kernel<1><<<gemmGrid256, 256>>>(q, op_w, op_b, src, offs, M, 256, 256);
    ln_kernel<<<cdiv(M * 32, 256), 256>>>(offs, ln1_g, ln1_b, out_x, M);
    // 7) text K/V
    kv_proj_kernel<<<B_SZ * LT, 256>>>(text, ipw, ipb, kh, vh);
    // 8) xp = x + pos -> val ; qh = xp @ wq^T + bq -> q
    add_kernel<<<cdiv(nElem, 256), 256>>>(out_x, pos, val, nElem);
    gemm_kernel<0><<<gemmGrid256, 256>>>(val, ipw, ipb, nullptr, q, M, 256, 256);
    // 9) cross attention -> ctx (reuse offs)
    cross_attn_kernel<<<cdiv(M * NH, 256), 256>>>(q, kh, vh, offs);
    // 10) pre-LN3 = ctx @ mo^T + b + x -> val ; LN3 -> out_x
    gemm_kernel<1><<<gemmGrid256, 256>>>(offs, mo_w, mo_b, out_x, val, M, 256, 256);
    ln_kernel<<<cdiv(M * 32, 256), 256>>>(val, ln3_g, ln3_b, out_x, M);
    // 11) FFN: hid = relu(x @ l1^T + b1); pre-LN2 = hid @ l2^T + b2 + x -> val ; LN2 -> out_x
    gemm_kernel<2><<<gemmGrid1024, 256>>>(out_x, l1_w, l1_b, nullptr, hid, M, DFF, 256);
    gemm_kernel<1><<<gemmGrid256, 256>>>(hid, l2_w, l2_b, out_x, val, M, 256, DFF);
    ln_kernel<<<cdiv(M * 32, 256), 256>>>(val, ln2_g, ln2_b, out_x, M);
    // 12) pass-through text_memory
    cudaMemcpyAsync(out_text, text, (size_t)B_SZ * LT * D_MODEL * sizeof(float),
                    cudaMemcpyDeviceToDevice, 0);
}

// round 4
// speedup vs baseline: 2.3876x; 2.3876x over previous
#include <cuda_runtime.h>
#include <cuda_bf16.h>
#include <cstdint>
#include <math.h>

// ---------------- problem constants ----------------
#define D_MODEL 256
#define NH 8
#define HD 32
#define NL 4
#define NP 4
#define DFF 1024
#define B_SZ 2
#define LT 20
#define LQ_C 20197
#define NTOK (B_SZ * LQ_C)   // 40394

__device__ __constant__ int c_H[NL]  = {100, 50, 25, 13};
__device__ __constant__ int c_W[NL]  = {152, 76, 38, 19};
__device__ __constant__ int c_St[NL] = {0, 15200, 19000, 19950};

// ---------------- scratch (static device globals; no allocation) ----------------
__device__ float g_q[NTOK * D_MODEL];
__device__ float g_value[NTOK * D_MODEL];
__device__ float g_offs[NTOK * D_MODEL];
__device__ float g_aw[NTOK * 128];
__device__ float g_hid[NTOK * DFF];
__device__ float g_kh[B_SZ * LT * D_MODEL];
__device__ float g_vh[B_SZ * LT * D_MODEL];

static inline int cdiv(int a, int b) { return (a + b - 1) / b; }

__device__ __forceinline__ uint32_t smem_u32(const void* p) {
    uint32_t a;
    asm("{ .reg .u64 t; cvta.to.shared.u64 t, %1; cvt.u32.u64 %0, t; }" : "=r"(a) : "l"(p));
    return a;
}

__device__ __forceinline__ void ldm_x4(uint32_t addr, uint32_t& r0, uint32_t& r1,
                                       uint32_t& r2, uint32_t& r3) {
    asm volatile("ldmatrix.sync.aligned.m8n8.x4.shared.b16 {%0,%1,%2,%3}, [%4];"
                 : "=r"(r0), "=r"(r1), "=r"(r2), "=r"(r3) : "r"(addr));
}

__device__ __forceinline__ void mma_bf16(float* c, const uint32_t* a, const uint32_t* b) {
    asm volatile(
        "mma.sync.aligned.m16n8k16.row.col.f32.bf16.bf16.f32 "
        "{%0,%1,%2,%3}, {%4,%5,%6,%7}, {%8,%9}, {%0,%1,%2,%3};"
        : "+f"(c[0]), "+f"(c[1]), "+f"(c[2]), "+f"(c[3])
        : "r"(a[0]), "r"(a[1]), "r"(a[2]), "r"(a[3]), "r"(b[0]), "r"(b[1]));
}

__device__ __forceinline__ void split4(float4 v, uint2& h, uint2& l) {
    union U { __nv_bfloat16 b[4]; uint2 u; } H, L;
    H.b[0] = __float2bfloat16_rn(v.x);
    H.b[1] = __float2bfloat16_rn(v.y);
    H.b[2] = __float2bfloat16_rn(v.z);
    H.b[3] = __float2bfloat16_rn(v.w);
    L.b[0] = __float2bfloat16_rn(v.x - __bfloat162float(H.b[0]));
    L.b[1] = __float2bfloat16_rn(v.y - __bfloat162float(H.b[1]));
    L.b[2] = __float2bfloat16_rn(v.z - __bfloat162float(H.b[2]));
    L.b[3] = __float2bfloat16_rn(v.w - __bfloat162float(H.b[3]));
    h = H.u; l = L.u;
}

// =====================================================================
// bf16-split tensor-core GEMM: C[M,N] = A_eff[M,K] @ W[N,K]^T + bias
//   A_eff = A (+ A2 if non-null)
//   MODE 0: +bias   1: +bias+residual   2: +bias,relu   3: +bias,softmax16
//   CTA 128x128, 8 warps (4x2, warp tile 32x64), K-chunk 64, 2 smem stages.
// =====================================================================
#define KC 64
#define TILE_B (128 * KC * 2)          // 16 KB per bf16 tile
#define STAGE_B (4 * TILE_B)           // Ah, Al, Bh, Bl = 64 KB
#define GEMM_SMEM (2 * STAGE_B)        // 128 KB

template <int MODE>
__global__ void __launch_bounds__(256, 1)
tc_gemm(const float* __restrict__ A, const float* __restrict__ A2,
        const float* __restrict__ W, const float* __restrict__ bias,
        const float* __restrict__ R, float* __restrict__ C,
        int M, int N, int K) {
    extern __shared__ char smem[];
    const uint32_t sbase = smem_u32(smem);
    const int tid = threadIdx.x;
    const int wid = tid >> 5;
    const int lane = tid & 31;
    const int rowBase = blockIdx.y * 128;
    const int colBase = blockIdx.x * 128;
    const int warpM = wid >> 1;        // 0..3 -> 32-row slab
    const int warpN = wid & 1;         // 0..1 -> 64-col slab

    float acc[2][8][4];
#pragma unroll
    for (int mi = 0; mi < 2; mi++)
#pragma unroll
        for (int ni = 0; ni < 8; ni++)
#pragma unroll
            for (int j = 0; j < 4; j++) acc[mi][ni][j] = 0.f;

    // --- STS addressing (per thread): row r = sRow + j*16, float4 chunk sC4 ---
    const int sRow = tid >> 4;
    const int sC4 = tid & 15;

    // --- ldmatrix per-lane offsets ---
    uint32_t aRowOff[2], bRowOff[4];
    int aKB0, bKB0;
    {
        int ar = (lane & 15);
        aKB0 = (lane >> 4) * 16;
#pragma unroll
        for (int mi = 0; mi < 2; mi++) {
            int r = warpM * 32 + mi * 16 + ar;
            aRowOff[mi] = (uint32_t)(r * 128);
        }
        int grp = lane >> 3;
        bKB0 = (grp & 1) * 16;
#pragma unroll
        for (int np = 0; np < 4; np++) {
            int n = warpN * 64 + np * 16 + ((grp >> 1) << 3) + (lane & 7);
            bRowOff[np] = (uint32_t)(n * 128);
        }
    }
    const int aSwX = ((warpM * 32 + (lane & 15)) & 7) << 4;   // mi*16 preserves r&7
    int bSwX[4];
#pragma unroll
    for (int np = 0; np < 4; np++)
        bSwX[np] = ((warpN * 64 + np * 16 + (((lane >> 3) >> 1) << 3) + (lane & 7)) & 7) << 4;

    const int nChunks = K / KC;
    float4 pa[8], pb[8];

    // prefetch chunk 0
#pragma unroll
    for (int j = 0; j < 8; j++) {
        int r = sRow + j * 16;
        int gr = rowBase + r;
        pa[j] = make_float4(0.f, 0.f, 0.f, 0.f);
        if (gr < M) {
            pa[j] = *(const float4*)(A + (size_t)gr * K + sC4 * 4);
            if (A2) {
                float4 a2 = *(const float4*)(A2 + (size_t)gr * K + sC4 * 4);
                pa[j].x += a2.x; pa[j].y += a2.y; pa[j].z += a2.z; pa[j].w += a2.w;
            }
        }
        pb[j] = *(const float4*)(W + (size_t)(colBase + r) * K + sC4 * 4);
    }

    for (int kt = 0; kt < nChunks; kt++) {
        const uint32_t stgOff = (uint32_t)((kt & 1) * STAGE_B);
        // ---- STS split tiles ----
#pragma unroll
        for (int j = 0; j < 8; j++) {
            int r = sRow + j * 16;
            uint32_t off = (uint32_t)(r * 128 + ((sC4 * 8) ^ ((r & 7) << 4)));
            uint2 h, l;
            split4(pa[j], h, l);
            *(uint2*)(smem + stgOff + off) = h;
            *(uint2*)(smem + stgOff + TILE_B + off) = l;
            split4(pb[j], h, l);
            *(uint2*)(smem + stgOff + 2 * TILE_B + off) = h;
            *(uint2*)(smem + stgOff + 3 * TILE_B + off) = l;
        }
        __syncthreads();
        // ---- prefetch next chunk (overlaps MMA below) ----
        if (kt + 1 < nChunks) {
            int k0 = (kt + 1) * KC;
#pragma unroll
            for (int j = 0; j < 8; j++) {
                int r = sRow + j * 16;
                int gr = rowBase + r;
                pa[j] = make_float4(0.f, 0.f, 0.f, 0.f);
                if (gr < M) {
                    pa[j] = *(const float4*)(A + (size_t)gr * K + k0 + sC4 * 4);
                    if (A2) {
                        float4 a2 = *(const float4*)(A2 + (size_t)gr * K + k0 + sC4 * 4);
                        pa[j].x += a2.x; pa[j].y += a2.y; pa[j].z += a2.z; pa[j].w += a2.w;
                    }
                }
                pb[j] = *(const float4*)(W + (size_t)(colBase + r) * K + k0 + sC4 * 4);
            }
        }
        // ---- MMA over 4 k-steps of 16 ----
        const uint32_t Ah = sbase + stgOff, Al = Ah + TILE_B;
        const uint32_t Bh = Ah + 2 * TILE_B, Bl = Ah + 3 * TILE_B;
#pragma unroll
        for (int kst = 0; kst < 4; kst++) {
            uint32_t ah[2][4], al[2][4];
#pragma unroll
            for (int mi = 0; mi < 2; mi++) {
                int kb = aKB0 + kst * 32;
                uint32_t off = aRowOff[mi] + (uint32_t)(kb ^ aSwX);
                ldm_x4(Ah + off, ah[mi][0], ah[mi][1], ah[mi][2], ah[mi][3]);
                ldm_x4(Al + off, al[mi][0], al[mi][1], al[mi][2], al[mi][3]);
            }
            uint32_t bh[8][2], bl[8][2];
#pragma unroll
            for (int np = 0; np < 4; np++) {
                int kb = bKB0 + kst * 32;
                uint32_t off = bRowOff[np] + (uint32_t)(kb ^ bSwX[np]);
                uint32_t r0, r1, r2, r3;
                ldm_x4(Bh + off, r0, r1, r2, r3);
                bh[np * 2][0] = r0; bh[np * 2][1] = r1;
                bh[np * 2 + 1][0] = r2; bh[np * 2 + 1][1] = r3;
                ldm_x4(Bl + off, r0, r1, r2, r3);
                bl[np * 2][0] = r0; bl[np * 2][1] = r1;
                bl[np * 2 + 1][0] = r2; bl[np * 2 + 1][1] = r3;
            }
#pragma unroll
            for (int mi = 0; mi < 2; mi++)
#pragma unroll
                for (int ni = 0; ni < 8; ni++) mma_bf16(acc[mi][ni], ah[mi], bh[ni]);
#pragma unroll
            for (int mi = 0; mi < 2; mi++)
#pragma unroll
                for (int ni = 0; ni < 8; ni++) mma_bf16(acc[mi][ni], ah[mi], bl[ni]);
#pragma unroll
            for (int mi = 0; mi < 2; mi++)
#pragma unroll
                for (int ni = 0; ni < 8; ni++) mma_bf16(acc[mi][ni], al[mi], bh[ni]);
        }
    }

    // ---- epilogue ----
    const int qrow = lane >> 2;        // 0..7
    const int qcol = (lane & 3) * 2;   // 0,2,4,6
#pragma unroll
    for (int ni = 0; ni < 8; ni++) {
        int col = colBase + warpN * 64 + ni * 8 + qcol;
        float b0 = __ldg(bias + col), b1 = __ldg(bias + col + 1);
#pragma unroll
        for (int mi = 0; mi < 2; mi++) {
            acc[mi][ni][0] += b0; acc[mi][ni][1] += b1;
            acc[mi][ni][2] += b0; acc[mi][ni][3] += b1;
        }
    }
    if (MODE == 3) {
        // softmax over 16-col groups: group g covers n-tiles 2g, 2g+1
#pragma unroll
        for (int mi = 0; mi < 2; mi++)
#pragma unroll
            for (int g = 0; g < 4; g++)
#pragma unroll
                for (int rh = 0; rh < 2; rh++) {
                    float v0 = acc[mi][2 * g][rh * 2], v1 = acc[mi][2 * g][rh * 2 + 1];
                    float v2 = acc[mi][2 * g + 1][rh * 2], v3 = acc[mi][2 * g + 1][rh * 2 + 1];
                    float mx = fmaxf(fmaxf(v0, v1), fmaxf(v2, v3));
                    mx = fmaxf(mx, __shfl_xor_sync(0xffffffffu, mx, 1));
                    mx = fmaxf(mx, __shfl_xor_sync(0xffffffffu, mx, 2));
                    v0 = expf(v0 - mx); v1 = expf(v1 - mx);
                    v2 = expf(v2 - mx); v3 = expf(v3 - mx);
                    float s = v0 + v1 + v2 + v3;
                    s += __shfl_xor_sync(0xffffffffu, s, 1);
                    s += __shfl_xor_sync(0xffffffffu, s, 2);
                    float inv = 1.f / s;
                    acc[mi][2 * g][rh * 2] = v0 * inv; acc[mi][2 * g][rh * 2 + 1] = v1 * inv;
                    acc[mi][2 * g + 1][rh * 2] = v2 * inv; acc[mi][2 * g + 1][rh * 2 + 1] = v3 * inv;
                }
    }
#pragma unroll
    for (int mi = 0; mi < 2; mi++)
#pragma unroll
        for (int rh = 0; rh < 2; rh++) {
            int row = rowBase + warpM * 32 + mi * 16 + qrow + rh * 8;
            if (row >= M) continue;
#pragma unroll
            for (int ni = 0; ni < 8; ni++) {
                int col = colBase + warpN * 64 + ni * 8 + qcol;
                float v0 = acc[mi][ni][rh * 2], v1 = acc[mi][ni][rh * 2 + 1];
                if (MODE == 1) {
                    const float2 rr = *(const float2*)(R + (size_t)row * N + col);
                    v0 += rr.x; v1 += rr.y;
                }
                if (MODE == 2) { v0 = fmaxf(v0, 0.f); v1 = fmaxf(v1, 0.f); }
                *(float2*)(C + (size_t)row * N + col) = make_float2(v0, v1);
            }
        }
}

// ---------------- multi-scale deformable sampling: warp per (token, head) ----------------
__global__ void msdeform_kernel(const float* __restrict__ value, const float* __restrict__ offs,
                                const float* __restrict__ aw, const float* __restrict__ ref,
                                float* __restrict__ out) {
    int gw = (blockIdx.x * blockDim.x + threadIdx.x) >> 5;
    int lane = threadIdx.x & 31;
    if (gw >= NTOK * NH) return;
    int token = gw >> 3, h = gw & 7;
    int b = token / LQ_C;

    const float* rp = ref + (long)token * (NL * 2);
    const float* of = offs + (long)token * 256 + h * 32;
    const float* awp = aw + (long)token * 128 + h * 16;

    float acc = 0.f;
#pragma unroll
    for (int l = 0; l < NL; l++) {
        int Wl = c_W[l], Hl = c_H[l];
        float Wf = (float)Wl, Hf = (float)Hl;
        float rx = rp[l * 2 + 0], ry = rp[l * 2 + 1];
        long base = (long)b * LQ_C + c_St[l];
#pragma unroll
        for (int p = 0; p < NP; p++) {
            float ox = of[(l * 4 + p) * 2 + 0];
            float oy = of[(l * 4 + p) * 2 + 1];
            float wA = awp[l * 4 + p];
            float X = (rx + ox / Wf) * Wf - 0.5f;
            float Y = (ry + oy / Hf) * Hf - 0.5f;
            float x0f = floorf(X), y0f = floorf(Y);
            float lx = X - x0f, ly = Y - y0f;
            int x0 = (int)x0f, y0 = (int)y0f;
            float ps = 0.f;
            {
                float w = (1.f - lx) * (1.f - ly);
                if (x0 >= 0 && x0 < Wl && y0 >= 0 && y0 < Hl)
                    ps += w * value[(base + (long)y0 * Wl + x0) * 256 + h * 32 + lane];
            }
            {
                float w = lx * (1.f - ly);
                int xi = x0 + 1;
                if (xi >= 0 && xi < Wl && y0 >= 0 && y0 < Hl)
                    ps += w * value[(base + (long)y0 * Wl + xi) * 256 + h * 32 + lane];
            }
            {
                float w = (1.f - lx) * ly;
                int yi = y0 + 1;
                if (x0 >= 0 && x0 < Wl && yi >= 0 && yi < Hl)
                    ps += w * value[(base + (long)yi * Wl + x0) * 256 + h * 32 + lane];
            }
            {
                float w = lx * ly;
                int xi = x0 + 1, yi = y0 + 1;
                if (xi >= 0 && xi < Wl && yi >= 0 && yi < Hl)
                    ps += w * value[(base + (long)yi * Wl + xi) * 256 + h * 32 + lane];
            }
            acc += wA * ps;
        }
    }
    out[(long)token * 256 + h * 32 + lane] = acc;
}

// ---------------- layernorm: warp per row (256 cols) ----------------
__global__ void ln_kernel(const float* __restrict__ in, const float* __restrict__ g,
                          const float* __restrict__ b, float* __restrict__ out, int rows) {
    int warp = (blockIdx.x * blockDim.x + threadIdx.x) >> 5;
    int lane = threadIdx.x & 31;
    if (warp >= rows) return;
    const float* x = in + (long)warp * 256;
    float v[8];
    float s = 0.f;
#pragma unroll
    for (int j = 0; j < 8; j++) { v[j] = x[j * 32 + lane]; s += v[j]; }
#pragma unroll
    for (int o = 16; o; o >>= 1) s += __shfl_xor_sync(0xffffffffu, s, o);
    float m = s * (1.f / 256.f);
    float s2 = 0.f;
#pragma unroll
    for (int j = 0; j < 8; j++) { float d = v[j] - m; s2 += d * d; }
#pragma unroll
    for (int o = 16; o; o >>= 1) s2 += __shfl_xor_sync(0xffffffffu, s2, o);
    float rstd = rsqrtf(s2 * (1.f / 256.f) + 1e-5f);
#pragma unroll
    for (int j = 0; j < 8; j++) {
        int col = j * 32 + lane;
        out[(long)warp * 256 + col] = (v[j] - m) * rstd * g[col] + b[col];
    }
}

// ---------------- text K/V projection (40 rows) ----------------
__global__ void kv_proj_kernel(const float* __restrict__ text, const float* __restrict__ ipw,
                               const float* __restrict__ ipb, float* __restrict__ kh,
                               float* __restrict__ vh) {
    int row = blockIdx.x;
    int c = threadIdx.x;
    const float* t = text + (long)row * 256;
    const float* wk = ipw + (long)(256 + c) * 256;
    const float* wv = ipw + (long)(512 + c) * 256;
    float sk = ipb[256 + c], sv = ipb[512 + c];
    for (int k = 0; k < 256; k++) {
        float tv = t[k];
        sk += tv * wk[k];
        sv += tv * wv[k];
    }
    kh[(long)row * 256 + c] = sk;
    vh[(long)row * 256 + c] = sv;
}

// ---------------- text cross-attention: thread per (token, head), K=20 ----------------
__global__ void cross_attn_kernel(const float* __restrict__ qh, const float* __restrict__ kh,
                                  const float* __restrict__ vh, float* __restrict__ ctx) {
    int idx = blockIdx.x * blockDim.x + threadIdx.x;
    if (idx >= NTOK * NH) return;
    int token = idx >> 3, h = idx & 7;
    int b = token / LQ_C;
    const float* q = qh + (long)token * 256 + h * 32;
    float qv[32];
#pragma unroll
    for (int d = 0; d < 32; d++) qv[d] = q[d];

    float sc[LT];
    float mx = -1e30f;
    const float scale = 0.17677669529663687f;
#pragma unroll 4
    for (int k = 0; k < LT; k++) {
        const float* kp = kh + (long)(b * LT + k) * 256 + h * 32;
        float s = 0.f;
#pragma unroll
        for (int d = 0; d < 32; d++) s += qv[d] * kp[d];
        s *= scale;
        sc[k] = s;
        mx = fmaxf(mx, s);
    }
    float denom = 0.f;
#pragma unroll
    for (int k = 0; k < LT; k++) { sc[k] = expf(sc[k] - mx); denom += sc[k]; }
    float inv = 1.f / denom;
    float o[32];
#pragma unroll
    for (int d = 0; d < 32; d++) o[d] = 0.f;
#pragma unroll 4
    for (int k = 0; k < LT; k++) {
        float p = sc[k] * inv;
        const float* vp = vh + (long)(b * LT + k) * 256 + h * 32;
#pragma unroll
        for (int d = 0; d < 32; d++) o[d] += p * vp[d];
    }
#pragma unroll
    for (int d = 0; d < 32; d++) ctx[(long)token * 256 + h * 32 + d] = o[d];
}

// ---------------- launch ----------------
extern "C" void kernel_launch(void* const* d_in, const int* in_sizes, int n_in,
                              void* d_out, int out_size) {
    const float* src   = (const float*)d_in[0];
    const float* pos   = (const float*)d_in[1];
    const float* refp  = (const float*)d_in[2];
    const float* text  = (const float*)d_in[5];
    const float* so_w  = (const float*)d_in[7];
    const float* so_b  = (const float*)d_in[8];
    const float* aw_w  = (const float*)d_in[9];
    const float* aw_b  = (const float*)d_in[10];
    const float* vp_w  = (const float*)d_in[11];
    const float* vp_b  = (const float*)d_in[12];
    const float* op_w  = (const float*)d_in[13];
    const float* op_b  = (const float*)d_in[14];
    const float* ln1_g = (const float*)d_in[15];
    const float* ln1_b = (const float*)d_in[16];
    const float* ipw   = (const float*)d_in[17];
    const float* ipb   = (const float*)d_in[18];
    const float* mo_w  = (const float*)d_in[19];
    const float* mo_b  = (const float*)d_in[20];
    const float* ln3_g = (const float*)d_in[21];
    const float* ln3_b = (const float*)d_in[22];
    const float* l1_w  = (const float*)d_in[23];
    const float* l1_b  = (const float*)d_in[24];
    const float* l2_w  = (const float*)d_in[25];
    const float* l2_b  = (const float*)d_in[26];
    const float* ln2_g = (const float*)d_in[27];
    const float* ln2_b = (const float*)d_in[28];

    float* out_x = (float*)d_out;
    float* out_text = out_x + (long)NTOK * D_MODEL;

    float *q, *val, *offs, *aw, *hid, *kh, *vh;
    cudaGetSymbolAddress((void**)&q, g_q);
    cudaGetSymbolAddress((void**)&val, g_value);
    cudaGetSymbolAddress((void**)&offs, g_offs);
    cudaGetSymbolAddress((void**)&aw, g_aw);
    cudaGetSymbolAddress((void**)&hid, g_hid);
    cudaGetSymbolAddress((void**)&kh, g_kh);
    cudaGetSymbolAddress((void**)&vh, g_vh);

    cudaFuncSetAttribute(tc_gemm<0>, cudaFuncAttributeMaxDynamicSharedMemorySize, GEMM_SMEM);
    cudaFuncSetAttribute(tc_gemm<1>, cudaFuncAttributeMaxDynamicSharedMemorySize, GEMM_SMEM);
    cudaFuncSetAttribute(tc_gemm<2>, cudaFuncAttributeMaxDynamicSharedMemorySize, GEMM_SMEM);
    cudaFuncSetAttribute(tc_gemm<3>, cudaFuncAttributeMaxDynamicSharedMemorySize, GEMM_SMEM);

    const int M = NTOK;
    const int mTiles = cdiv(M, 128);
    dim3 g256(2, mTiles), g128(1, mTiles), g1024(8, mTiles);

    // 1) value = src @ vp^T + b
    tc_gemm<0><<<g256, 256, GEMM_SMEM>>>(src, nullptr, vp_w, vp_b, nullptr, val, M, 256, 256);
    // 2) offs = (src+pos) @ so^T + b
    tc_gemm<0><<<g256, 256, GEMM_SMEM>>>(src, pos, so_w, so_b, nullptr, offs, M, 256, 256);
    // 3) aw = softmax16((src+pos) @ aw^T + b)
    tc_gemm<3><<<g128, 256, GEMM_SMEM>>>(src, pos, aw_w, aw_b, nullptr, aw, M, 128, 256);
    // 4) deformable sampling -> q (reused as ms output)
    msdeform_kernel<<<cdiv(M * NH * 32, 256), 256>>>(val, offs, aw, refp, q);
    // 5) pre-LN1 = ms @ op^T + b + src -> offs ; LN1 -> out_x
    tc_gemm<1><<<g256, 256, GEMM_SMEM>>>(q, nullptr, op_w, op_b, src, offs, M, 256, 256);
    ln_kernel<<<cdiv(M * 32, 256), 256>>>(offs, ln1_g, ln1_b, out_x, M);
    // 6) text K/V
    kv_proj_kernel<<<B_SZ * LT, 256>>>(text, ipw, ipb, kh, vh);
    // 7) qh = (x+pos) @ wq^T + bq -> q
    tc_gemm<0><<<g256, 256, GEMM_SMEM>>>(out_x, pos, ipw, ipb, nullptr, q, M, 256, 256);
    // 8) cross attention -> offs (reused as ctx)
    cross_attn_kernel<<<cdiv(M * NH, 256), 256>>>(q, kh, vh, offs);
    // 9) pre-LN3 = ctx @ mo^T + b + x -> val ; LN3 -> out_x
    tc_gemm<1><<<g256, 256, GEMM_SMEM>>>(offs, nullptr, mo_w, mo_b, out_x, val, M, 256, 256);
    ln_kernel<<<cdiv(M * 32, 256), 256>>>(val, ln3_g, ln3_b, out_x, M);
    // 10) FFN
    tc_gemm<2><<<g1024, 256, GEMM_SMEM>>>(out_x, nullptr, l1_w, l1_b, nullptr, hid, M, DFF, 256);
    tc_gemm<1><<<g256, 256, GEMM_SMEM>>>(hid, nullptr, l2_w, l2_b, out_x, val, M, 256, DFF);
    ln_kernel<<<cdiv(M * 32, 256), 256>>>(val, ln2_g, ln2_b, out_x, M);
    // 11) pass-through text_memory
    cudaMemcpyAsync(out_text, text, (size_t)B_SZ * LT * D_MODEL * sizeof(float),
                    cudaMemcpyDeviceToDevice, 0);
}

// round 5
// speedup vs baseline: 2.9391x; 1.2310x over previous
#include <cuda_runtime.h>
#include <cuda_bf16.h>
#include <cstdint>
#include <math.h>

// ---------------- problem constants ----------------
#define D_MODEL 256
#define NH 8
#define HD 32
#define NL 4
#define NP 4
#define DFF 1024
#define B_SZ 2
#define LT 20
#define LQ_C 20197
#define NTOK (B_SZ * LQ_C)   // 40394

__device__ __constant__ int c_H[NL]  = {100, 50, 25, 13};
__device__ __constant__ int c_W[NL]  = {152, 76, 38, 19};
__device__ __constant__ int c_St[NL] = {0, 15200, 19000, 19950};

// ---------------- scratch (static device globals; no allocation) ----------------
__device__ float g_q[NTOK * D_MODEL];
__device__ float g_value[NTOK * D_MODEL];
__device__ float g_offs[NTOK * D_MODEL];
__device__ float g_aw[NTOK * 128];
__device__ float g_hid[NTOK * DFF];
__device__ float g_kh[B_SZ * LT * D_MODEL];
__device__ float g_vh[B_SZ * LT * D_MODEL];

static inline int cdiv(int a, int b) { return (a + b - 1) / b; }

__device__ __forceinline__ uint32_t smem_u32(const void* p) {
    uint32_t a;
    asm("{ .reg .u64 t; cvta.to.shared.u64 t, %1; cvt.u32.u64 %0, t; }" : "=r"(a) : "l"(p));
    return a;
}

__device__ __forceinline__ void ldm_x4(uint32_t addr, uint32_t& r0, uint32_t& r1,
                                       uint32_t& r2, uint32_t& r3) {
    asm volatile("ldmatrix.sync.aligned.m8n8.x4.shared.b16 {%0,%1,%2,%3}, [%4];"
                 : "=r"(r0), "=r"(r1), "=r"(r2), "=r"(r3) : "r"(addr));
}

__device__ __forceinline__ void mma_bf16(float* c, const uint32_t* a, const uint32_t* b) {
    asm volatile(
        "mma.sync.aligned.m16n8k16.row.col.f32.bf16.bf16.f32 "
        "{%0,%1,%2,%3}, {%4,%5,%6,%7}, {%8,%9}, {%0,%1,%2,%3};"
        : "+f"(c[0]), "+f"(c[1]), "+f"(c[2]), "+f"(c[3])
        : "r"(a[0]), "r"(a[1]), "r"(a[2]), "r"(a[3]), "r"(b[0]), "r"(b[1]));
}

__device__ __forceinline__ void split4(float4 v, uint2& h, uint2& l) {
    union U { __nv_bfloat16 b[4]; uint2 u; } H, L;
    H.b[0] = __float2bfloat16_rn(v.x);
    H.b[1] = __float2bfloat16_rn(v.y);
    H.b[2] = __float2bfloat16_rn(v.z);
    H.b[3] = __float2bfloat16_rn(v.w);
    L.b[0] = __float2bfloat16_rn(v.x - __bfloat162float(H.b[0]));
    L.b[1] = __float2bfloat16_rn(v.y - __bfloat162float(H.b[1]));
    L.b[2] = __float2bfloat16_rn(v.z - __bfloat162float(H.b[2]));
    L.b[3] = __float2bfloat16_rn(v.w - __bfloat162float(H.b[3]));
    h = H.u; l = L.u;
}

// =====================================================================
// bf16-split tensor-core GEMM: C[M,N] = A_eff[M,K] @ W[N,K]^T + bias
//   A_eff = A (+ A2 if non-null)
//   MODE 0: +bias   1: +bias+residual   2: +bias,relu   3: +bias,softmax16
//   CTA 128x128, 8 warps (4x2, warp tile 32x64), K-chunk 64, 2 smem stages.
// =====================================================================
#define KC 64
#define TILE_B (128 * KC * 2)          // 16 KB per bf16 tile
#define STAGE_B (4 * TILE_B)           // Ah, Al, Bh, Bl = 64 KB
#define GEMM_SMEM (2 * STAGE_B)        // 128 KB

template <int MODE>
__global__ void __launch_bounds__(256, 1)
tc_gemm(const float* __restrict__ A, const float* __restrict__ A2,
        const float* __restrict__ W, const float* __restrict__ bias,
        const float* __restrict__ R, float* __restrict__ C,
        int M, int N, int K) {
    extern __shared__ char smem[];
    const uint32_t sbase = smem_u32(smem);
    const int tid = threadIdx.x;
    const int wid = tid >> 5;
    const int lane = tid & 31;
    const int rowBase = blockIdx.y * 128;
    const int colBase = blockIdx.x * 128;
    const int warpM = wid >> 1;        // 0..3 -> 32-row slab
    const int warpN = wid & 1;         // 0..1 -> 64-col slab

    float acc[2][8][4];
#pragma unroll
    for (int mi = 0; mi < 2; mi++)
#pragma unroll
        for (int ni = 0; ni < 8; ni++)
#pragma unroll
            for (int j = 0; j < 4; j++) acc[mi][ni][j] = 0.f;

    const int sRow = tid >> 4;
    const int sC4 = tid & 15;

    uint32_t aRowOff[2], bRowOff[4];
    int aKB0, bKB0;
    {
        int ar = (lane & 15);
        aKB0 = (lane >> 4) * 16;
#pragma unroll
        for (int mi = 0; mi < 2; mi++) {
            int r = warpM * 32 + mi * 16 + ar;
            aRowOff[mi] = (uint32_t)(r * 128);
        }
        int grp = lane >> 3;
        bKB0 = (grp & 1) * 16;
#pragma unroll
        for (int np = 0; np < 4; np++) {
            int n = warpN * 64 + np * 16 + ((grp >> 1) << 3) + (lane & 7);
            bRowOff[np] = (uint32_t)(n * 128);
        }
    }
    const int aSwX = ((warpM * 32 + (lane & 15)) & 7) << 4;
    int bSwX[4];
#pragma unroll
    for (int np = 0; np < 4; np++)
        bSwX[np] = ((warpN * 64 + np * 16 + (((lane >> 3) >> 1) << 3) + (lane & 7)) & 7) << 4;

    const int nChunks = K / KC;
    float4 pa[8], pb[8];

    // prefetch chunk 0
#pragma unroll
    for (int j = 0; j < 8; j++) {
        int r = sRow + j * 16;
        int gr = rowBase + r;
        pa[j] = make_float4(0.f, 0.f, 0.f, 0.f);
        if (gr < M) {
            pa[j] = *(const float4*)(A + (size_t)gr * K + sC4 * 4);
            if (A2) {
                float4 a2 = *(const float4*)(A2 + (size_t)gr * K + sC4 * 4);
                pa[j].x += a2.x; pa[j].y += a2.y; pa[j].z += a2.z; pa[j].w += a2.w;
            }
        }
        pb[j] = *(const float4*)(W + (size_t)(colBase + r) * K + sC4 * 4);
    }

    for (int kt = 0; kt < nChunks; kt++) {
        const uint32_t stgOff = (uint32_t)((kt & 1) * STAGE_B);
#pragma unroll
        for (int j = 0; j < 8; j++) {
            int r = sRow + j * 16;
            uint32_t off = (uint32_t)(r * 128 + ((sC4 * 8) ^ ((r & 7) << 4)));
            uint2 h, l;
            split4(pa[j], h, l);
            *(uint2*)(smem + stgOff + off) = h;
            *(uint2*)(smem + stgOff + TILE_B + off) = l;
            split4(pb[j], h, l);
            *(uint2*)(smem + stgOff + 2 * TILE_B + off) = h;
            *(uint2*)(smem + stgOff + 3 * TILE_B + off) = l;
        }
        __syncthreads();
        if (kt + 1 < nChunks) {
            int k0 = (kt + 1) * KC;
#pragma unroll
            for (int j = 0; j < 8; j++) {
                int r = sRow + j * 16;
                int gr = rowBase + r;
                pa[j] = make_float4(0.f, 0.f, 0.f, 0.f);
                if (gr < M) {
                    pa[j] = *(const float4*)(A + (size_t)gr * K + k0 + sC4 * 4);
                    if (A2) {
                        float4 a2 = *(const float4*)(A2 + (size_t)gr * K + k0 + sC4 * 4);
                        pa[j].x += a2.x; pa[j].y += a2.y; pa[j].z += a2.z; pa[j].w += a2.w;
                    }
                }
                pb[j] = *(const float4*)(W + (size_t)(colBase + r) * K + k0 + sC4 * 4);
            }
        }
        const uint32_t Ah = sbase + stgOff, Al = Ah + TILE_B;
        const uint32_t Bh = Ah + 2 * TILE_B, Bl = Ah + 3 * TILE_B;
#pragma unroll
        for (int kst = 0; kst < 4; kst++) {
            uint32_t ah[2][4], al[2][4];
#pragma unroll
            for (int mi = 0; mi < 2; mi++) {
                int kb = aKB0 + kst * 32;
                uint32_t off = aRowOff[mi] + (uint32_t)(kb ^ aSwX);
                ldm_x4(Ah + off, ah[mi][0], ah[mi][1], ah[mi][2], ah[mi][3]);
                ldm_x4(Al + off, al[mi][0], al[mi][1], al[mi][2], al[mi][3]);
            }
            uint32_t bh[8][2], bl[8][2];
#pragma unroll
            for (int np = 0; np < 4; np++) {
                int kb = bKB0 + kst * 32;
                uint32_t off = bRowOff[np] + (uint32_t)(kb ^ bSwX[np]);
                uint32_t r0, r1, r2, r3;
                ldm_x4(Bh + off, r0, r1, r2, r3);
                bh[np * 2][0] = r0; bh[np * 2][1] = r1;
                bh[np * 2 + 1][0] = r2; bh[np * 2 + 1][1] = r3;
                ldm_x4(Bl + off, r0, r1, r2, r3);
                bl[np * 2][0] = r0; bl[np * 2][1] = r1;
                bl[np * 2 + 1][0] = r2; bl[np * 2 + 1][1] = r3;
            }
#pragma unroll
            for (int mi = 0; mi < 2; mi++)
#pragma unroll
                for (int ni = 0; ni < 8; ni++) mma_bf16(acc[mi][ni], ah[mi], bh[ni]);
#pragma unroll
            for (int mi = 0; mi < 2; mi++)
#pragma unroll
                for (int ni = 0; ni < 8; ni++) mma_bf16(acc[mi][ni], ah[mi], bl[ni]);
#pragma unroll
            for (int mi = 0; mi < 2; mi++)
#pragma unroll
                for (int ni = 0; ni < 8; ni++) mma_bf16(acc[mi][ni], al[mi], bh[ni]);
        }
    }

    // ---- epilogue ----
    const int qrow = lane >> 2;
    const int qcol = (lane & 3) * 2;
#pragma unroll
    for (int ni = 0; ni < 8; ni++) {
        int col = colBase + warpN * 64 + ni * 8 + qcol;
        float b0 = __ldg(bias + col), b1 = __ldg(bias + col + 1);
#pragma unroll
        for (int mi = 0; mi < 2; mi++) {
            acc[mi][ni][0] += b0; acc[mi][ni][1] += b1;
            acc[mi][ni][2] += b0; acc[mi][ni][3] += b1;
        }
    }
    if (MODE == 3) {
#pragma unroll
        for (int mi = 0; mi < 2; mi++)
#pragma unroll
            for (int g = 0; g < 4; g++)
#pragma unroll
                for (int rh = 0; rh < 2; rh++) {
                    float v0 = acc[mi][2 * g][rh * 2], v1 = acc[mi][2 * g][rh * 2 + 1];
                    float v2 = acc[mi][2 * g + 1][rh * 2], v3 = acc[mi][2 * g + 1][rh * 2 + 1];
                    float mx = fmaxf(fmaxf(v0, v1), fmaxf(v2, v3));
                    mx = fmaxf(mx, __shfl_xor_sync(0xffffffffu, mx, 1));
                    mx = fmaxf(mx, __shfl_xor_sync(0xffffffffu, mx, 2));
                    v0 = expf(v0 - mx); v1 = expf(v1 - mx);
                    v2 = expf(v2 - mx); v3 = expf(v3 - mx);
                    float s = v0 + v1 + v2 + v3;
                    s += __shfl_xor_sync(0xffffffffu, s, 1);
                    s += __shfl_xor_sync(0xffffffffu, s, 2);
                    float inv = 1.f / s;
                    acc[mi][2 * g][rh * 2] = v0 * inv; acc[mi][2 * g][rh * 2 + 1] = v1 * inv;
                    acc[mi][2 * g + 1][rh * 2] = v2 * inv; acc[mi][2 * g + 1][rh * 2 + 1] = v3 * inv;
                }
    }
#pragma unroll
    for (int mi = 0; mi < 2; mi++)
#pragma unroll
        for (int rh = 0; rh < 2; rh++) {
            int row = rowBase + warpM * 32 + mi * 16 + qrow + rh * 8;
            if (row >= M) continue;
#pragma unroll
            for (int ni = 0; ni < 8; ni++) {
                int col = colBase + warpN * 64 + ni * 8 + qcol;
                float v0 = acc[mi][ni][rh * 2], v1 = acc[mi][ni][rh * 2 + 1];
                if (MODE == 1) {
                    const float2 rr = *(const float2*)(R + (size_t)row * N + col);
                    v0 += rr.x; v1 += rr.y;
                }
                if (MODE == 2) { v0 = fmaxf(v0, 0.f); v1 = fmaxf(v1, 0.f); }
                *(float2*)(C + (size_t)row * N + col) = make_float2(v0, v1);
            }
        }
}

// ---------------- multi-scale deformable sampling (lane-parallel setup) ----------------
// Warp per (token, head). Lanes 0..15 each own one sampling point: compute 4
// clipped row indices + 4 validity-masked weights (pre-multiplied by attn w).
// Then 16-step gather loop broadcasts point data via shfl; all 32 lanes load
// one channel each (coalesced 128B per corner).
__global__ void msdeform_kernel(const float* __restrict__ value, const float* __restrict__ offs,
                                const float* __restrict__ aw, const float* __restrict__ ref,
                                float* __restrict__ out) {
    int gw = (blockIdx.x * blockDim.x + threadIdx.x) >> 5;
    int lane = threadIdx.x & 31;
    if (gw >= NTOK * NH) return;
    int token = gw >> 3, h = gw & 7;
    int b = (token >= LQ_C) ? 1 : 0;

    // ---- per-lane point setup (p = lane & 15; lanes 16-31 duplicate) ----
    int p = lane & 15;
    int l = p >> 2;
    int Wl = c_W[l], Hl = c_H[l];
    float Wf = (float)Wl, Hf = (float)Hl;
    float rx = __ldg(ref + (size_t)token * 8 + l * 2);
    float ry = __ldg(ref + (size_t)token * 8 + l * 2 + 1);
    float ox = __ldg(offs + (size_t)token * 256 + h * 32 + p * 2);
    float oy = __ldg(offs + (size_t)token * 256 + h * 32 + p * 2 + 1);
    float wA = __ldg(aw + (size_t)token * 128 + h * 16 + p);

    float X = (rx + ox / Wf) * Wf - 0.5f;
    float Y = (ry + oy / Hf) * Hf - 0.5f;
    float x0f = floorf(X), y0f = floorf(Y);
    float lx = X - x0f, ly = Y - y0f;
    int x0 = (int)x0f, y0 = (int)y0f;
    int x1 = x0 + 1, y1 = y0 + 1;
    bool vx0 = (x0 >= 0) & (x0 < Wl), vx1 = (x1 >= 0) & (x1 < Wl);
    bool vy0 = (y0 >= 0) & (y0 < Hl), vy1 = (y1 >= 0) & (y1 < Hl);
    int cx0 = min(max(x0, 0), Wl - 1), cx1 = min(max(x1, 0), Wl - 1);
    int cy0 = min(max(y0, 0), Hl - 1), cy1 = min(max(y1, 0), Hl - 1);
    int base = b * LQ_C + c_St[l];
    int r00 = base + cy0 * Wl + cx0;
    int r01 = base + cy0 * Wl + cx1;
    int r10 = base + cy1 * Wl + cx0;
    int r11 = base + cy1 * Wl + cx1;
    float w00 = wA * (1.f - lx) * (1.f - ly) * (float)(vx0 & vy0);
    float w01 = wA * lx * (1.f - ly) * (float)(vx1 & vy0);
    float w10 = wA * (1.f - lx) * ly * (float)(vx0 & vy1);
    float w11 = wA * lx * ly * (float)(vx1 & vy1);

    // ---- gather: broadcast each point's data, all lanes load channels ----
    const float* vb = value + h * 32 + lane;
    float acc = 0.f;
#pragma unroll
    for (int pp = 0; pp < 16; pp++) {
        int s00 = __shfl_sync(0xffffffffu, r00, pp);
        int s01 = __shfl_sync(0xffffffffu, r01, pp);
        int s10 = __shfl_sync(0xffffffffu, r10, pp);
        int s11 = __shfl_sync(0xffffffffu, r11, pp);
        float u00 = __shfl_sync(0xffffffffu, w00, pp);
        float u01 = __shfl_sync(0xffffffffu, w01, pp);
        float u10 = __shfl_sync(0xffffffffu, w10, pp);
        float u11 = __shfl_sync(0xffffffffu, w11, pp);
        acc += u00 * __ldg(vb + (size_t)s00 * 256);
        acc += u01 * __ldg(vb + (size_t)s01 * 256);
        acc += u10 * __ldg(vb + (size_t)s10 * 256);
        acc += u11 * __ldg(vb + (size_t)s11 * 256);
    }
    out[(size_t)token * 256 + h * 32 + lane] = acc;
}

// ---------------- layernorm: warp per row (256 cols) ----------------
__global__ void ln_kernel(const float* __restrict__ in, const float* __restrict__ g,
                          const float* __restrict__ b, float* __restrict__ out, int rows) {
    int warp = (blockIdx.x * blockDim.x + threadIdx.x) >> 5;
    int lane = threadIdx.x & 31;
    if (warp >= rows) return;
    const float* x = in + (long)warp * 256;
    float v[8];
    float s = 0.f;
#pragma unroll
    for (int j = 0; j < 8; j++) { v[j] = x[j * 32 + lane]; s += v[j]; }
#pragma unroll
    for (int o = 16; o; o >>= 1) s += __shfl_xor_sync(0xffffffffu, s, o);
    float m = s * (1.f / 256.f);
    float s2 = 0.f;
#pragma unroll
    for (int j = 0; j < 8; j++) { float d = v[j] - m; s2 += d * d; }
#pragma unroll
    for (int o = 16; o; o >>= 1) s2 += __shfl_xor_sync(0xffffffffu, s2, o);
    float rstd = rsqrtf(s2 * (1.f / 256.f) + 1e-5f);
#pragma unroll
    for (int j = 0; j < 8; j++) {
        int col = j * 32 + lane;
        out[(long)warp * 256 + col] = (v[j] - m) * rstd * g[col] + b[col];
    }
}

// ---------------- text K/V projection (40 rows) ----------------
__global__ void kv_proj_kernel(const float* __restrict__ text, const float* __restrict__ ipw,
                               const float* __restrict__ ipb, float* __restrict__ kh,
                               float* __restrict__ vh) {
    int row = blockIdx.x;
    int c = threadIdx.x;
    const float* t = text + (long)row * 256;
    const float* wk = ipw + (long)(256 + c) * 256;
    const float* wv = ipw + (long)(512 + c) * 256;
    float sk = ipb[256 + c], sv = ipb[512 + c];
    for (int k = 0; k < 256; k++) {
        float tv = t[k];
        sk += tv * wk[k];
        sv += tv * wv[k];
    }
    kh[(long)row * 256 + c] = sk;
    vh[(long)row * 256 + c] = sv;
}

// ---------------- text cross-attention: thread per (token, head), K=20, float4 ----------------
__global__ void cross_attn_kernel(const float* __restrict__ qh, const float* __restrict__ kh,
                                  const float* __restrict__ vh, float* __restrict__ ctx) {
    int idx = blockIdx.x * blockDim.x + threadIdx.x;
    if (idx >= NTOK * NH) return;
    int token = idx >> 3, h = idx & 7;
    int b = (token >= LQ_C) ? 1 : 0;
    const float4* q = (const float4*)(qh + (size_t)token * 256 + h * 32);
    float4 qv[8];
#pragma unroll
    for (int j = 0; j < 8; j++) qv[j] = q[j];

    float sc[LT];
    float mx = -1e30f;
    const float scale = 0.17677669529663687f;
#pragma unroll 4
    for (int k = 0; k < LT; k++) {
        const float4* kp = (const float4*)(kh + (size_t)(b * LT + k) * 256 + h * 32);
        float s = 0.f;
#pragma unroll
        for (int j = 0; j < 8; j++) {
            float4 kv = kp[j];
            s += qv[j].x * kv.x + qv[j].y * kv.y + qv[j].z * kv.z + qv[j].w * kv.w;
        }
        s *= scale;
        sc[k] = s;
        mx = fmaxf(mx, s);
    }
    float denom = 0.f;
#pragma unroll
    for (int k = 0; k < LT; k++) { sc[k] = expf(sc[k] - mx); denom += sc[k]; }
    float inv = 1.f / denom;
    float4 o[8];
#pragma unroll
    for (int j = 0; j < 8; j++) o[j] = make_float4(0.f, 0.f, 0.f, 0.f);
#pragma unroll 4
    for (int k = 0; k < LT; k++) {
        float pw = sc[k] * inv;
        const float4* vp = (const float4*)(vh + (size_t)(b * LT + k) * 256 + h * 32);
#pragma unroll
        for (int j = 0; j < 8; j++) {
            float4 vv = vp[j];
            o[j].x += pw * vv.x; o[j].y += pw * vv.y;
            o[j].z += pw * vv.z; o[j].w += pw * vv.w;
        }
    }
    float4* cp = (float4*)(ctx + (size_t)token * 256 + h * 32);
#pragma unroll
    for (int j = 0; j < 8; j++) cp[j] = o[j];
}

// ---------------- launch ----------------
extern "C" void kernel_launch(void* const* d_in, const int* in_sizes, int n_in,
                              void* d_out, int out_size) {
    const float* src   = (const float*)d_in[0];
    const float* pos   = (const float*)d_in[1];
    const float* refp  = (const float*)d_in[2];
    const float* text  = (const float*)d_in[5];
    const float* so_w  = (const float*)d_in[7];
    const float* so_b  = (const float*)d_in[8];
    const float* aw_w  = (const float*)d_in[9];
    const float* aw_b  = (const float*)d_in[10];
    const float* vp_w  = (const float*)d_in[11];
    const float* vp_b  = (const float*)d_in[12];
    const float* op_w  = (const float*)d_in[13];
    const float* op_b  = (const float*)d_in[14];
    const float* ln1_g = (const float*)d_in[15];
    const float* ln1_b = (const float*)d_in[16];
    const float* ipw   = (const float*)d_in[17];
    const float* ipb   = (const float*)d_in[18];
    const float* mo_w  = (const float*)d_in[19];
    const float* mo_b  = (const float*)d_in[20];
    const float* ln3_g = (const float*)d_in[21];
    const float* ln3_b = (const float*)d_in[22];
    const float* l1_w  = (const float*)d_in[23];
    const float* l1_b  = (const float*)d_in[24];
    const float* l2_w  = (const float*)d_in[25];
    const float* l2_b  = (const float*)d_in[26];
    const float* ln2_g = (const float*)d_in[27];
    const float* ln2_b = (const float*)d_in[28];

    float* out_x = (float*)d_out;
    float* out_text = out_x + (long)NTOK * D_MODEL;

    float *q, *val, *offs, *aw, *hid, *kh, *vh;
    cudaGetSymbolAddress((void**)&q, g_q);
    cudaGetSymbolAddress((void**)&val, g_value);
    cudaGetSymbolAddress((void**)&offs, g_offs);
    cudaGetSymbolAddress((void**)&aw, g_aw);
    cudaGetSymbolAddress((void**)&hid, g_hid);
    cudaGetSymbolAddress((void**)&kh, g_kh);
    cudaGetSymbolAddress((void**)&vh, g_vh);

    cudaFuncSetAttribute(tc_gemm<0>, cudaFuncAttributeMaxDynamicSharedMemorySize, GEMM_SMEM);
    cudaFuncSetAttribute(tc_gemm<1>, cudaFuncAttributeMaxDynamicSharedMemorySize, GEMM_SMEM);
    cudaFuncSetAttribute(tc_gemm<2>, cudaFuncAttributeMaxDynamicSharedMemorySize, GEMM_SMEM);
    cudaFuncSetAttribute(tc_gemm<3>, cudaFuncAttributeMaxDynamicSharedMemorySize, GEMM_SMEM);

    const int M = NTOK;
    const int mTiles = cdiv(M, 128);
    dim3 g256(2, mTiles), g128(1, mTiles), g1024(8, mTiles);

    // 1) value = src @ vp^T + b
    tc_gemm<0><<<g256, 256, GEMM_SMEM>>>(src, nullptr, vp_w, vp_b, nullptr, val, M, 256, 256);
    // 2) offs = (src+pos) @ so^T + b
    tc_gemm<0><<<g256, 256, GEMM_SMEM>>>(src, pos, so_w, so_b, nullptr, offs, M, 256, 256);
    // 3) aw = softmax16((src+pos) @ aw^T + b)
    tc_gemm<3><<<g128, 256, GEMM_SMEM>>>(src, pos, aw_w, aw_b, nullptr, aw, M, 128, 256);
    // 4) deformable sampling -> q (reused as ms output)
    msdeform_kernel<<<cdiv(M * NH * 32, 256), 256>>>(val, offs, aw, refp, q);
    // 5) pre-LN1 = ms @ op^T + b + src -> offs ; LN1 -> out_x
    tc_gemm<1><<<g256, 256, GEMM_SMEM>>>(q, nullptr, op_w, op_b, src, offs, M, 256, 256);
    ln_kernel<<<cdiv(M * 32, 256), 256>>>(offs, ln1_g, ln1_b, out_x, M);
    // 6) text K/V
    kv_proj_kernel<<<B_SZ * LT, 256>>>(text, ipw, ipb, kh, vh);
    // 7) qh = (x+pos) @ wq^T + bq -> q
    tc_gemm<0><<<g256, 256, GEMM_SMEM>>>(out_x, pos, ipw, ipb, nullptr, q, M, 256, 256);
    // 8) cross attention -> offs (reused as ctx)
    cross_attn_kernel<<<cdiv(M * NH, 256), 256>>>(q, kh, vh, offs);
    // 9) pre-LN3 = ctx @ mo^T + b + x -> val ; LN3 -> out_x
    tc_gemm<1><<<g256, 256, GEMM_SMEM>>>(offs, nullptr, mo_w, mo_b, out_x, val, M, 256, 256);
    ln_kernel<<<cdiv(M * 32, 256), 256>>>(val, ln3_g, ln3_b, out_x, M);
    // 10) FFN
    tc_gemm<2><<<g1024, 256, GEMM_SMEM>>>(out_x, nullptr, l1_w, l1_b, nullptr, hid, M, DFF, 256);
    tc_gemm<1><<<g256, 256, GEMM_SMEM>>>(hid, nullptr, l2_w, l2_b, out_x, val, M, 256, DFF);
    ln_kernel<<<cdiv(M * 32, 256), 256>>>(val, ln2_g, ln2_b, out_x, M);
    // 11) pass-through text_memory
    cudaMemcpyAsync(out_text, text, (size_t)B_SZ * LT * D_MODEL * sizeof(float),
                    cudaMemcpyDeviceToDevice, 0);
}

// round 6
// speedup vs baseline: 3.2230x; 1.0966x over previous
#include <cuda_runtime.h>
#include <cuda_bf16.h>
#include <cstdint>
#include <math.h>

// ---------------- problem constants ----------------
#define D_MODEL 256
#define NH 8
#define HD 32
#define NL 4
#define NP 4
#define DFF 1024
#define B_SZ 2
#define LT 20
#define LQ_C 20197
#define NTOK (B_SZ * LQ_C)   // 40394

__device__ __constant__ int c_H[NL]  = {100, 50, 25, 13};
__device__ __constant__ int c_W[NL]  = {152, 76, 38, 19};
__device__ __constant__ int c_St[NL] = {0, 15200, 19000, 19950};

// ---------------- scratch (static device globals; no allocation) ----------------
__device__ float g_q[NTOK * D_MODEL];
__device__ float g_value[NTOK * D_MODEL];
__device__ float g_offs[NTOK * D_MODEL];
__device__ float g_aw[NTOK * 128];
__device__ float g_hid[NTOK * DFF];
__device__ float g_kh[B_SZ * LT * D_MODEL];
__device__ float g_vh[B_SZ * LT * D_MODEL];

static inline int cdiv(int a, int b) { return (a + b - 1) / b; }

__device__ __forceinline__ uint32_t smem_u32(const void* p) {
    uint32_t a;
    asm("{ .reg .u64 t; cvta.to.shared.u64 t, %1; cvt.u32.u64 %0, t; }" : "=r"(a) : "l"(p));
    return a;
}

__device__ __forceinline__ void ldm_x4(uint32_t addr, uint32_t& r0, uint32_t& r1,
                                       uint32_t& r2, uint32_t& r3) {
    asm volatile("ldmatrix.sync.aligned.m8n8.x4.shared.b16 {%0,%1,%2,%3}, [%4];"
                 : "=r"(r0), "=r"(r1), "=r"(r2), "=r"(r3) : "r"(addr));
}

__device__ __forceinline__ void mma_bf16(float* c, const uint32_t* a, const uint32_t* b) {
    asm volatile(
        "mma.sync.aligned.m16n8k16.row.col.f32.bf16.bf16.f32 "
        "{%0,%1,%2,%3}, {%4,%5,%6,%7}, {%8,%9}, {%0,%1,%2,%3};"
        : "+f"(c[0]), "+f"(c[1]), "+f"(c[2]), "+f"(c[3])
        : "r"(a[0]), "r"(a[1]), "r"(a[2]), "r"(a[3]), "r"(b[0]), "r"(b[1]));
}

__device__ __forceinline__ void split4(float4 v, uint2& h, uint2& l) {
    union U { __nv_bfloat16 b[4]; uint2 u; } H, L;
    H.b[0] = __float2bfloat16_rn(v.x);
    H.b[1] = __float2bfloat16_rn(v.y);
    H.b[2] = __float2bfloat16_rn(v.z);
    H.b[3] = __float2bfloat16_rn(v.w);
    L.b[0] = __float2bfloat16_rn(v.x - __bfloat162float(H.b[0]));
    L.b[1] = __float2bfloat16_rn(v.y - __bfloat162float(H.b[1]));
    L.b[2] = __float2bfloat16_rn(v.z - __bfloat162float(H.b[2]));
    L.b[3] = __float2bfloat16_rn(v.w - __bfloat162float(H.b[3]));
    h = H.u; l = L.u;
}

// =====================================================================
// bf16-split tensor-core GEMM: C[M,N] = A_eff[M,K] @ W[N,K]^T + bias
//   A_eff = A (+ A2 if non-null)
//   MODE 0: +bias   1: +bias+residual   2: +bias,relu   3: +bias,softmax16
//   CTA tile 64(M) x 128(N), 256 thr (8 warps, warp tile 32x32),
//   K-chunk 64, 2 smem stages (48KB each) -> 2 CTAs/SM.
// =====================================================================
#define KC 64
#define A_TILE_B (64 * 128)            // 8 KB  (64 rows x 64 bf16)
#define B_TILE_B (128 * 128)           // 16 KB (128 rows x 64 bf16)
#define STAGE_B (2 * A_TILE_B + 2 * B_TILE_B)  // 48 KB: Ah, Al, Bh, Bl
#define GEMM_SMEM (2 * STAGE_B)        // 96 KB

template <int MODE>
__global__ void __launch_bounds__(256, 2)
tc_gemm(const float* __restrict__ A, const float* __restrict__ A2,
        const float* __restrict__ W, const float* __restrict__ bias,
        const float* __restrict__ R, float* __restrict__ C,
        int M, int N, int K) {
    extern __shared__ char smem[];
    const uint32_t sbase = smem_u32(smem);
    const int tid = threadIdx.x;
    const int wid = tid >> 5;
    const int lane = tid & 31;
    const int rowBase = blockIdx.y * 64;
    const int colBase = blockIdx.x * 128;
    const int warpM = wid >> 2;        // 0..1 -> 32-row slab
    const int warpN = wid & 3;         // 0..3 -> 32-col slab

    float acc[2][4][4];
#pragma unroll
    for (int mi = 0; mi < 2; mi++)
#pragma unroll
        for (int ni = 0; ni < 4; ni++)
#pragma unroll
            for (int j = 0; j < 4; j++) acc[mi][ni][j] = 0.f;

    const int sRow = tid >> 4;         // 0..15
    const int sC4 = tid & 15;

    // ldmatrix per-lane offsets; all swizzle XORs reduce to (lane&7)<<4
    const uint32_t swX = (uint32_t)((lane & 7) << 4);
    const int aKB0 = (lane >> 4) * 16;
    uint32_t aRowOff[2];
#pragma unroll
    for (int mi = 0; mi < 2; mi++)
        aRowOff[mi] = (uint32_t)((warpM * 32 + mi * 16 + (lane & 15)) * 128);
    const int grp = lane >> 3;
    const int bKB0 = (grp & 1) * 16;
    uint32_t bRowOff[2];
#pragma unroll
    for (int np = 0; np < 2; np++)
        bRowOff[np] = (uint32_t)((warpN * 32 + np * 16 + ((grp >> 1) << 3) + (lane & 7)) * 128);

    const int nChunks = K / KC;
    float4 pa[4];

    // prefetch A chunk 0 (4 rows per thread)
#pragma unroll
    for (int j = 0; j < 4; j++) {
        int gr = rowBase + sRow + j * 16;
        pa[j] = make_float4(0.f, 0.f, 0.f, 0.f);
        if (gr < M) {
            pa[j] = *(const float4*)(A + (size_t)gr * K + sC4 * 4);
            if (A2) {
                float4 a2 = *(const float4*)(A2 + (size_t)gr * K + sC4 * 4);
                pa[j].x += a2.x; pa[j].y += a2.y; pa[j].z += a2.z; pa[j].w += a2.w;
            }
        }
    }

    for (int kt = 0; kt < nChunks; kt++) {
        const uint32_t stgOff = (uint32_t)((kt & 1) * STAGE_B);
        const int k0 = kt * KC;
        // ---- B: load directly (L2-resident weights) + split + STS ----
#pragma unroll
        for (int j = 0; j < 8; j++) {
            int r = sRow + j * 16;     // 0..127
            uint32_t off = (uint32_t)(r * 128 + ((sC4 * 8) ^ ((r & 7) << 4)));
            float4 wv = *(const float4*)(W + (size_t)(colBase + r) * K + k0 + sC4 * 4);
            uint2 h, l;
            split4(wv, h, l);
            *(uint2*)(smem + stgOff + 2 * A_TILE_B + off) = h;
            *(uint2*)(smem + stgOff + 2 * A_TILE_B + B_TILE_B + off) = l;
        }
        // ---- A: split prefetched regs + STS ----
#pragma unroll
        for (int j = 0; j < 4; j++) {
            int r = sRow + j * 16;     // 0..63
            uint32_t off = (uint32_t)(r * 128 + ((sC4 * 8) ^ ((r & 7) << 4)));
            uint2 h, l;
            split4(pa[j], h, l);
            *(uint2*)(smem + stgOff + off) = h;
            *(uint2*)(smem + stgOff + A_TILE_B + off) = l;
        }
        __syncthreads();
        // ---- prefetch next A chunk (overlaps MMA below) ----
        if (kt + 1 < nChunks) {
            int kn = k0 + KC;
#pragma unroll
            for (int j = 0; j < 4; j++) {
                int gr = rowBase + sRow + j * 16;
                pa[j] = make_float4(0.f, 0.f, 0.f, 0.f);
                if (gr < M) {
                    pa[j] = *(const float4*)(A + (size_t)gr * K + kn + sC4 * 4);
                    if (A2) {
                        float4 a2 = *(const float4*)(A2 + (size_t)gr * K + kn + sC4 * 4);
                        pa[j].x += a2.x; pa[j].y += a2.y; pa[j].z += a2.z; pa[j].w += a2.w;
                    }
                }
            }
        }
        // ---- MMA over 4 k-steps of 16 ----
        const uint32_t Ah = sbase + stgOff, Al = Ah + A_TILE_B;
        const uint32_t Bh = Ah + 2 * A_TILE_B, Bl = Bh + B_TILE_B;
#pragma unroll
        for (int kst = 0; kst < 4; kst++) {
            uint32_t ah[2][4], al[2][4];
#pragma unroll
            for (int mi = 0; mi < 2; mi++) {
                uint32_t off = aRowOff[mi] + (uint32_t)((aKB0 + kst * 32) ^ swX);
                ldm_x4(Ah + off, ah[mi][0], ah[mi][1], ah[mi][2], ah[mi][3]);
                ldm_x4(Al + off, al[mi][0], al[mi][1], al[mi][2], al[mi][3]);
            }
            uint32_t bh[4][2], bl[4][2];
#pragma unroll
            for (int np = 0; np < 2; np++) {
                uint32_t off = bRowOff[np] + (uint32_t)((bKB0 + kst * 32) ^ swX);
                uint32_t r0, r1, r2, r3;
                ldm_x4(Bh + off, r0, r1, r2, r3);
                bh[np * 2][0] = r0; bh[np * 2][1] = r1;
                bh[np * 2 + 1][0] = r2; bh[np * 2 + 1][1] = r3;
                ldm_x4(Bl + off, r0, r1, r2, r3);
                bl[np * 2][0] = r0; bl[np * 2][1] = r1;
                bl[np * 2 + 1][0] = r2; bl[np * 2 + 1][1] = r3;
            }
#pragma unroll
            for (int mi = 0; mi < 2; mi++)
#pragma unroll
                for (int ni = 0; ni < 4; ni++) mma_bf16(acc[mi][ni], ah[mi], bh[ni]);
#pragma unroll
            for (int mi = 0; mi < 2; mi++)
#pragma unroll
                for (int ni = 0; ni < 4; ni++) mma_bf16(acc[mi][ni], ah[mi], bl[ni]);
#pragma unroll
            for (int mi = 0; mi < 2; mi++)
#pragma unroll
                for (int ni = 0; ni < 4; ni++) mma_bf16(acc[mi][ni], al[mi], bh[ni]);
        }
        if (kt + 1 < nChunks) __syncthreads();
    }

    // ---- epilogue ----
    const int qrow = lane >> 2;
    const int qcol = (lane & 3) * 2;
#pragma unroll
    for (int ni = 0; ni < 4; ni++) {
        int col = colBase + warpN * 32 + ni * 8 + qcol;
        float b0 = __ldg(bias + col), b1 = __ldg(bias + col + 1);
#pragma unroll
        for (int mi = 0; mi < 2; mi++) {
            acc[mi][ni][0] += b0; acc[mi][ni][1] += b1;
            acc[mi][ni][2] += b0; acc[mi][ni][3] += b1;
        }
    }
    if (MODE == 3) {
        // softmax over 16-col groups: group g covers n-tiles 2g, 2g+1
#pragma unroll
        for (int mi = 0; mi < 2; mi++)
#pragma unroll
            for (int g = 0; g < 2; g++)
#pragma unroll
                for (int rh = 0; rh < 2; rh++) {
                    float v0 = acc[mi][2 * g][rh * 2], v1 = acc[mi][2 * g][rh * 2 + 1];
                    float v2 = acc[mi][2 * g + 1][rh * 2], v3 = acc[mi][2 * g + 1][rh * 2 + 1];
                    float mx = fmaxf(fmaxf(v0, v1), fmaxf(v2, v3));
                    mx = fmaxf(mx, __shfl_xor_sync(0xffffffffu, mx, 1));
                    mx = fmaxf(mx, __shfl_xor_sync(0xffffffffu, mx, 2));
                    v0 = expf(v0 - mx); v1 = expf(v1 - mx);
                    v2 = expf(v2 - mx); v3 = expf(v3 - mx);
                    float s = v0 + v1 + v2 + v3;
                    s += __shfl_xor_sync(0xffffffffu, s, 1);
                    s += __shfl_xor_sync(0xffffffffu, s, 2);
                    float inv = 1.f / s;
                    acc[mi][2 * g][rh * 2] = v0 * inv; acc[mi][2 * g][rh * 2 + 1] = v1 * inv;
                    acc[mi][2 * g + 1][rh * 2] = v2 * inv; acc[mi][2 * g + 1][rh * 2 + 1] = v3 * inv;
                }
    }
#pragma unroll
    for (int mi = 0; mi < 2; mi++)
#pragma unroll
        for (int rh = 0; rh < 2; rh++) {
            int row = rowBase + warpM * 32 + mi * 16 + qrow + rh * 8;
            if (row >= M) continue;
#pragma unroll
            for (int ni = 0; ni < 4; ni++) {
                int col = colBase + warpN * 32 + ni * 8 + qcol;
                float v0 = acc[mi][ni][rh * 2], v1 = acc[mi][ni][rh * 2 + 1];
                if (MODE == 1) {
                    const float2 rr = *(const float2*)(R + (size_t)row * N + col);
                    v0 += rr.x; v1 += rr.y;
                }
                if (MODE == 2) { v0 = fmaxf(v0, 0.f); v1 = fmaxf(v1, 0.f); }
                *(float2*)(C + (size_t)row * N + col) = make_float2(v0, v1);
            }
        }
}

// ---------------- multi-scale deformable sampling (lane-parallel setup) ----------------
__global__ void msdeform_kernel(const float* __restrict__ value, const float* __restrict__ offs,
                                const float* __restrict__ aw, const float* __restrict__ ref,
                                float* __restrict__ out) {
    int gw = (blockIdx.x * blockDim.x + threadIdx.x) >> 5;
    int lane = threadIdx.x & 31;
    if (gw >= NTOK * NH) return;
    int token = gw >> 3, h = gw & 7;
    int b = (token >= LQ_C) ? 1 : 0;

    int p = lane & 15;
    int l = p >> 2;
    int Wl = c_W[l], Hl = c_H[l];
    float Wf = (float)Wl, Hf = (float)Hl;
    float rx = __ldg(ref + (size_t)token * 8 + l * 2);
    float ry = __ldg(ref + (size_t)token * 8 + l * 2 + 1);
    float ox = __ldg(offs + (size_t)token * 256 + h * 32 + p * 2);
    float oy = __ldg(offs + (size_t)token * 256 + h * 32 + p * 2 + 1);
    float wA = __ldg(aw + (size_t)token * 128 + h * 16 + p);

    float X = (rx + ox / Wf) * Wf - 0.5f;
    float Y = (ry + oy / Hf) * Hf - 0.5f;
    float x0f = floorf(X), y0f = floorf(Y);
    float lx = X - x0f, ly = Y - y0f;
    int x0 = (int)x0f, y0 = (int)y0f;
    int x1 = x0 + 1, y1 = y0 + 1;
    bool vx0 = (x0 >= 0) & (x0 < Wl), vx1 = (x1 >= 0) & (x1 < Wl);
    bool vy0 = (y0 >= 0) & (y0 < Hl), vy1 = (y1 >= 0) & (y1 < Hl);
    int cx0 = min(max(x0, 0), Wl - 1), cx1 = min(max(x1, 0), Wl - 1);
    int cy0 = min(max(y0, 0), Hl - 1), cy1 = min(max(y1, 0), Hl - 1);
    int base = b * LQ_C + c_St[l];
    int r00 = base + cy0 * Wl + cx0;
    int r01 = base + cy0 * Wl + cx1;
    int r10 = base + cy1 * Wl + cx0;
    int r11 = base + cy1 * Wl + cx1;
    float w00 = wA * (1.f - lx) * (1.f - ly) * (float)(vx0 & vy0);
    float w01 = wA * lx * (1.f - ly) * (float)(vx1 & vy0);
    float w10 = wA * (1.f - lx) * ly * (float)(vx0 & vy1);
    float w11 = wA * lx * ly * (float)(vx1 & vy1);

    const float* vb = value + h * 32 + lane;
    float acc = 0.f;
#pragma unroll
    for (int pp = 0; pp < 16; pp++) {
        int s00 = __shfl_sync(0xffffffffu, r00, pp);
        int s01 = __shfl_sync(0xffffffffu, r01, pp);
        int s10 = __shfl_sync(0xffffffffu, r10, pp);
        int s11 = __shfl_sync(0xffffffffu, r11, pp);
        float u00 = __shfl_sync(0xffffffffu, w00, pp);
        float u01 = __shfl_sync(0xffffffffu, w01, pp);
        float u10 = __shfl_sync(0xffffffffu, w10, pp);
        float u11 = __shfl_sync(0xffffffffu, w11, pp);
        acc += u00 * __ldg(vb + (size_t)s00 * 256);
        acc += u01 * __ldg(vb + (size_t)s01 * 256);
        acc += u10 * __ldg(vb + (size_t)s10 * 256);
        acc += u11 * __ldg(vb + (size_t)s11 * 256);
    }
    out[(size_t)token * 256 + h * 32 + lane] = acc;
}

// ---------------- layernorm: warp per row (256 cols) ----------------
__global__ void ln_kernel(const float* __restrict__ in, const float* __restrict__ g,
                          const float* __restrict__ b, float* __restrict__ out, int rows) {
    int warp = (blockIdx.x * blockDim.x + threadIdx.x) >> 5;
    int lane = threadIdx.x & 31;
    if (warp >= rows) return;
    const float* x = in + (long)warp * 256;
    float v[8];
    float s = 0.f;
#pragma unroll
    for (int j = 0; j < 8; j++) { v[j] = x[j * 32 + lane]; s += v[j]; }
#pragma unroll
    for (int o = 16; o; o >>= 1) s += __shfl_xor_sync(0xffffffffu, s, o);
    float m = s * (1.f / 256.f);
    float s2 = 0.f;
#pragma unroll
    for (int j = 0; j < 8; j++) { float d = v[j] - m; s2 += d * d; }
#pragma unroll
    for (int o = 16; o; o >>= 1) s2 += __shfl_xor_sync(0xffffffffu, s2, o);
    float rstd = rsqrtf(s2 * (1.f / 256.f) + 1e-5f);
#pragma unroll
    for (int j = 0; j < 8; j++) {
        int col = j * 32 + lane;
        out[(long)warp * 256 + col] = (v[j] - m) * rstd * g[col] + b[col];
    }
}

// ---------------- text K/V projection (40 rows) ----------------
__global__ void kv_proj_kernel(const float* __restrict__ text, const float* __restrict__ ipw,
                               const float* __restrict__ ipb, float* __restrict__ kh,
                               float* __restrict__ vh) {
    int row = blockIdx.x;
    int c = threadIdx.x;
    const float* t = text + (long)row * 256;
    const float* wk = ipw + (long)(256 + c) * 256;
    const float* wv = ipw + (long)(512 + c) * 256;
    float sk = ipb[256 + c], sv = ipb[512 + c];
    for (int k = 0; k < 256; k++) {
        float tv = t[k];
        sk += tv * wk[k];
        sv += tv * wv[k];
    }
    kh[(long)row * 256 + c] = sk;
    vh[(long)row * 256 + c] = sv;
}

// ---------------- text cross-attention: thread per (token, head), K=20, float4 ----------------
__global__ void cross_attn_kernel(const float* __restrict__ qh, const float* __restrict__ kh,
                                  const float* __restrict__ vh, float* __restrict__ ctx) {
    int idx = blockIdx.x * blockDim.x + threadIdx.x;
    if (idx >= NTOK * NH) return;
    int token = idx >> 3, h = idx & 7;
    int b = (token >= LQ_C) ? 1 : 0;
    const float4* q = (const float4*)(qh + (size_t)token * 256 + h * 32);
    float4 qv[8];
#pragma unroll
    for (int j = 0; j < 8; j++) qv[j] = q[j];

    float sc[LT];
    float mx = -1e30f;
    const float scale = 0.17677669529663687f;
#pragma unroll 4
    for (int k = 0; k < LT; k++) {
        const float4* kp = (const float4*)(kh + (size_t)(b * LT + k) * 256 + h * 32);
        float s = 0.f;
#pragma unroll
        for (int j = 0; j < 8; j++) {
            float4 kv = kp[j];
            s += qv[j].x * kv.x + qv[j].y * kv.y + qv[j].z * kv.z + qv[j].w * kv.w;
        }
        s *= scale;
        sc[k] = s;
        mx = fmaxf(mx, s);
    }
    float denom = 0.f;
#pragma unroll
    for (int k = 0; k < LT; k++) { sc[k] = expf(sc[k] - mx); denom += sc[k]; }
    float inv = 1.f / denom;
    float4 o[8];
#pragma unroll
    for (int j = 0; j < 8; j++) o[j] = make_float4(0.f, 0.f, 0.f, 0.f);
#pragma unroll 4
    for (int k = 0; k < LT; k++) {
        float pw = sc[k] * inv;
        const float4* vp = (const float4*)(vh + (size_t)(b * LT + k) * 256 + h * 32);
#pragma unroll
        for (int j = 0; j < 8; j++) {
            float4 vv = vp[j];
            o[j].x += pw * vv.x; o[j].y += pw * vv.y;
            o[j].z += pw * vv.z; o[j].w += pw * vv.w;
        }
    }
    float4* cp = (float4*)(ctx + (size_t)token * 256 + h * 32);
#pragma unroll
    for (int j = 0; j < 8; j++) cp[j] = o[j];
}

// ---------------- launch ----------------
extern "C" void kernel_launch(void* const* d_in, const int* in_sizes, int n_in,
                              void* d_out, int out_size) {
    const float* src   = (const float*)d_in[0];
    const float* pos   = (const float*)d_in[1];
    const float* refp  = (const float*)d_in[2];
    const float* text  = (const float*)d_in[5];
    const float* so_w  = (const float*)d_in[7];
    const float* so_b  = (const float*)d_in[8];
    const float* aw_w  = (const float*)d_in[9];
    const float* aw_b  = (const float*)d_in[10];
    const float* vp_w  = (const float*)d_in[11];
    const float* vp_b  = (const float*)d_in[12];
    const float* op_w  = (const float*)d_in[13];
    const float* op_b  = (const float*)d_in[14];
    const float* ln1_g = (const float*)d_in[15];
    const float* ln1_b = (const float*)d_in[16];
    const float* ipw   = (const float*)d_in[17];
    const float* ipb   = (const float*)d_in[18];
    const float* mo_w  = (const float*)d_in[19];
    const float* mo_b  = (const float*)d_in[20];
    const float* ln3_g = (const float*)d_in[21];
    const float* ln3_b = (const float*)d_in[22];
    const float* l1_w  = (const float*)d_in[23];
    const float* l1_b  = (const float*)d_in[24];
    const float* l2_w  = (const float*)d_in[25];
    const float* l2_b  = (const float*)d_in[26];
    const float* ln2_g = (const float*)d_in[27];
    const float* ln2_b = (const float*)d_in[28];

    float* out_x = (float*)d_out;
    float* out_text = out_x + (long)NTOK * D_MODEL;

    float *q, *val, *offs, *aw, *hid, *kh, *vh;
    cudaGetSymbolAddress((void**)&q, g_q);
    cudaGetSymbolAddress((void**)&val, g_value);
    cudaGetSymbolAddress((void**)&offs, g_offs);
    cudaGetSymbolAddress((void**)&aw, g_aw);
    cudaGetSymbolAddress((void**)&hid, g_hid);
    cudaGetSymbolAddress((void**)&kh, g_kh);
    cudaGetSymbolAddress((void**)&vh, g_vh);

    cudaFuncSetAttribute(tc_gemm<0>, cudaFuncAttributeMaxDynamicSharedMemorySize, GEMM_SMEM);
    cudaFuncSetAttribute(tc_gemm<1>, cudaFuncAttributeMaxDynamicSharedMemorySize, GEMM_SMEM);
    cudaFuncSetAttribute(tc_gemm<2>, cudaFuncAttributeMaxDynamicSharedMemorySize, GEMM_SMEM);
    cudaFuncSetAttribute(tc_gemm<3>, cudaFuncAttributeMaxDynamicSharedMemorySize, GEMM_SMEM);

    const int M = NTOK;
    const int mTiles = cdiv(M, 64);    // 632
    dim3 g256(2, mTiles), g128(1, mTiles), g1024(8, mTiles);

    // 1) value = src @ vp^T + b
    tc_gemm<0><<<g256, 256, GEMM_SMEM>>>(src, nullptr, vp_w, vp_b, nullptr, val, M, 256, 256);
    // 2) offs = (src+pos) @ so^T + b
    tc_gemm<0><<<g256, 256, GEMM_SMEM>>>(src, pos, so_w, so_b, nullptr, offs, M, 256, 256);
    // 3) aw = softmax16((src+pos) @ aw^T + b)
    tc_gemm<3><<<g128, 256, GEMM_SMEM>>>(src, pos, aw_w, aw_b, nullptr, aw, M, 128, 256);
    // 4) deformable sampling -> q (reused as ms output)
    msdeform_kernel<<<cdiv(M * NH * 32, 256), 256>>>(val, offs, aw, refp, q);
    // 5) pre-LN1 = ms @ op^T + b + src -> offs ; LN1 -> out_x
    tc_gemm<1><<<g256, 256, GEMM_SMEM>>>(q, nullptr, op_w, op_b, src, offs, M, 256, 256);
    ln_kernel<<<cdiv(M * 32, 256), 256>>>(offs, ln1_g, ln1_b, out_x, M);
    // 6) text K/V
    kv_proj_kernel<<<B_SZ * LT, 256>>>(text, ipw, ipb, kh, vh);
    // 7) qh = (x+pos) @ wq^T + bq -> q
    tc_gemm<0><<<g256, 256, GEMM_SMEM>>>(out_x, pos, ipw, ipb, nullptr, q, M, 256, 256);
    // 8) cross attention -> offs (reused as ctx)
    cross_attn_kernel<<<cdiv(M * NH, 256), 256>>>(q, kh, vh, offs);
    // 9) pre-LN3 = ctx @ mo^T + b + x -> val ; LN3 -> out_x
    tc_gemm<1><<<g256, 256, GEMM_SMEM>>>(offs, nullptr, mo_w, mo_b, out_x, val, M, 256, 256);
    ln_kernel<<<cdiv(M * 32, 256), 256>>>(val, ln3_g, ln3_b, out_x, M);
    // 10) FFN
    tc_gemm<2><<<g1024, 256, GEMM_SMEM>>>(out_x, nullptr, l1_w, l1_b, nullptr, hid, M, DFF, 256);
    tc_gemm<1><<<g256, 256, GEMM_SMEM>>>(hid, nullptr, l2_w, l2_b, out_x, val, M, 256, DFF);
    ln_kernel<<<cdiv(M * 32, 256), 256>>>(val, ln2_g, ln2_b, out_x, M);
    // 11) pass-through text_memory
    cudaMemcpyAsync(out_text, text, (size_t)B_SZ * LT * D_MODEL * sizeof(float),
                    cudaMemcpyDeviceToDevice, 0);
}